// round 9
// baseline (speedup 1.0000x reference)
#include <cuda_runtime.h>
#include <cuda_bf16.h>
#include <cstdint>
#include <cstddef>
#include <math.h>

#define Bsz 16
#define Msz 512
#define HIDs 768
#define NH 12
#define HD 64
#define BHsz (Bsz*NH)

#define BM 128
#define BN 128
#define BK 32
#define ASTR 40
#define BSTR 136
#define NIT (HIDs/BK)
#define A_STAGE (BM*ASTR)
#define B_STAGE (BK*BSTR)
#define OFF_AH 0
#define OFF_AL (2*A_STAGE)
#define OFF_BH (4*A_STAGE)
#define OFF_BL (4*A_STAGE + 2*B_STAGE)
#define SMEM_BYTES ((4*A_STAGE + 4*B_STAGE) * 2)

// Scratch (__device__ globals; no allocation allowed)
__device__ float g_Q[(size_t)Bsz*Msz*HIDs];
__device__ __nv_bfloat16 g_Ah[(size_t)Bsz*Msz*HIDs];
__device__ __nv_bfloat16 g_Al[(size_t)Bsz*Msz*HIDs];
__device__ __nv_bfloat16 g_Wh[HIDs*HIDs];
__device__ __nv_bfloat16 g_Wl[HIDs*HIDs];
__device__ float g_s[BHsz*Msz];
__device__ float g_nasup[BHsz*Msz];
__device__ float g_nasub[BHsz*Msz];
__device__ float g_S[BHsz*Msz];

// ---------------------------------------------------------------------------
// Split fp32 -> bf16 hi + bf16 lo
// ---------------------------------------------------------------------------
__global__ void k_cvt(const float* __restrict__ x, __nv_bfloat16* __restrict__ hi,
                      __nv_bfloat16* __restrict__ lo, int n) {
    int idx = (blockIdx.x * blockDim.x + threadIdx.x) * 4;
    if (idx >= n) return;
    float4 v = *(const float4*)(x + idx);
    __nv_bfloat16 h0 = __float2bfloat16(v.x), h1 = __float2bfloat16(v.y);
    __nv_bfloat16 h2 = __float2bfloat16(v.z), h3 = __float2bfloat16(v.w);
    __nv_bfloat16 l0 = __float2bfloat16(v.x - __bfloat162float(h0));
    __nv_bfloat16 l1 = __float2bfloat16(v.y - __bfloat162float(h1));
    __nv_bfloat16 l2 = __float2bfloat16(v.z - __bfloat162float(h2));
    __nv_bfloat16 l3 = __float2bfloat16(v.w - __bfloat162float(h3));
    __nv_bfloat162 hp0, hp1, lp0, lp1;
    hp0.x = h0; hp0.y = h1; hp1.x = h2; hp1.y = h3;
    lp0.x = l0; lp0.y = l1; lp1.x = l2; lp1.y = l3;
    *(__nv_bfloat162*)(hi + idx)     = hp0;
    *(__nv_bfloat162*)(hi + idx + 2) = hp1;
    *(__nv_bfloat162*)(lo + idx)     = lp0;
    *(__nv_bfloat162*)(lo + idx + 2) = lp1;
}

// ---------------------------------------------------------------------------
// Helpers
// ---------------------------------------------------------------------------
__device__ __forceinline__ void cp16(__nv_bfloat16* s, const __nv_bfloat16* g) {
    unsigned sa = (unsigned)__cvta_generic_to_shared(s);
    asm volatile("cp.async.ca.shared.global [%0], [%1], 16;\n" :: "r"(sa), "l"(g));
}
__device__ __forceinline__ void ldm_x4(unsigned* r, unsigned a) {
    asm volatile("ldmatrix.sync.aligned.m8n8.x4.shared.b16 {%0,%1,%2,%3}, [%4];"
                 : "=r"(r[0]), "=r"(r[1]), "=r"(r[2]), "=r"(r[3]) : "r"(a));
}
__device__ __forceinline__ void ldm_x4_t(unsigned* r, unsigned a) {
    asm volatile("ldmatrix.sync.aligned.m8n8.x4.trans.shared.b16 {%0,%1,%2,%3}, [%4];"
                 : "=r"(r[0]), "=r"(r[1]), "=r"(r[2]), "=r"(r[3]) : "r"(a));
}
__device__ __forceinline__ void mma16816(float* c, const unsigned* a, const unsigned* b) {
    asm volatile(
        "mma.sync.aligned.m16n8k16.row.col.f32.bf16.bf16.f32 "
        "{%0,%1,%2,%3}, {%4,%5,%6,%7}, {%8,%9}, {%0,%1,%2,%3};"
        : "+f"(c[0]), "+f"(c[1]), "+f"(c[2]), "+f"(c[3])
        : "r"(a[0]), "r"(a[1]), "r"(a[2]), "r"(a[3]), "r"(b[0]), "r"(b[1]));
}
__device__ __forceinline__ void stcs4(float* p, float a, float b, float c, float d) {
    asm volatile("st.global.cs.v4.f32 [%0], {%1,%2,%3,%4};"
                 :: "l"(p), "f"(a), "f"(b), "f"(c), "f"(d) : "memory");
}

// ---------------------------------------------------------------------------
// K1: Q = X @ Wq + bq via bf16-split tensor cores (unchanged from R8)
// ---------------------------------------------------------------------------
__global__ __launch_bounds__(256) void k_gemm_mma(const float* __restrict__ bias) {
    extern __shared__ __align__(16) __nv_bfloat16 smem[];
    __nv_bfloat16* sAh = smem + OFF_AH;
    __nv_bfloat16* sAl = smem + OFF_AL;
    __nv_bfloat16* sBh = smem + OFF_BH;
    __nv_bfloat16* sBl = smem + OFF_BL;

    int tid  = threadIdx.x;
    int bm   = blockIdx.y * BM;
    int bn   = blockIdx.x * BN;
    int warp = tid >> 5, lane = tid & 31;
    int wm = (warp & 3) * 32;
    int wn = (warp >> 2) * 64;

    int arow = tid >> 1, acol = (tid & 1) * 16;
    int brow = tid >> 3, bcol = (tid & 7) * 16;

    float acc[2][8][4];
#pragma unroll
    for (int m = 0; m < 2; m++)
#pragma unroll
        for (int n = 0; n < 8; n++)
#pragma unroll
            for (int j = 0; j < 4; j++) acc[m][n][j] = 0.f;

    {
        const __nv_bfloat16* gah = g_Ah + (size_t)(bm + arow) * HIDs + acol;
        const __nv_bfloat16* gal = g_Al + (size_t)(bm + arow) * HIDs + acol;
        const __nv_bfloat16* gbh = g_Wh + (size_t)brow * HIDs + bn + bcol;
        const __nv_bfloat16* gbl = g_Wl + (size_t)brow * HIDs + bn + bcol;
        __nv_bfloat16* dah = sAh + arow * ASTR + acol;
        __nv_bfloat16* dal = sAl + arow * ASTR + acol;
        __nv_bfloat16* dbh = sBh + brow * BSTR + bcol;
        __nv_bfloat16* dbl = sBl + brow * BSTR + bcol;
        cp16(dah, gah); cp16(dah + 8, gah + 8);
        cp16(dal, gal); cp16(dal + 8, gal + 8);
        cp16(dbh, gbh); cp16(dbh + 8, gbh + 8);
        cp16(dbl, gbl); cp16(dbl + 8, gbl + 8);
        asm volatile("cp.async.commit_group;");
    }

    for (int it = 0; it < NIT; it++) {
        int s = it & 1;
        if (it + 1 < NIT) {
            int k0 = (it + 1) * BK, ns = s ^ 1;
            const __nv_bfloat16* gah = g_Ah + (size_t)(bm + arow) * HIDs + k0 + acol;
            const __nv_bfloat16* gal = g_Al + (size_t)(bm + arow) * HIDs + k0 + acol;
            const __nv_bfloat16* gbh = g_Wh + (size_t)(k0 + brow) * HIDs + bn + bcol;
            const __nv_bfloat16* gbl = g_Wl + (size_t)(k0 + brow) * HIDs + bn + bcol;
            __nv_bfloat16* dah = sAh + ns * A_STAGE + arow * ASTR + acol;
            __nv_bfloat16* dal = sAl + ns * A_STAGE + arow * ASTR + acol;
            __nv_bfloat16* dbh = sBh + ns * B_STAGE + brow * BSTR + bcol;
            __nv_bfloat16* dbl = sBl + ns * B_STAGE + brow * BSTR + bcol;
            cp16(dah, gah); cp16(dah + 8, gah + 8);
            cp16(dal, gal); cp16(dal + 8, gal + 8);
            cp16(dbh, gbh); cp16(dbh + 8, gbh + 8);
            cp16(dbl, gbl); cp16(dbl + 8, gbl + 8);
            asm volatile("cp.async.commit_group;");
            asm volatile("cp.async.wait_group 1;");
        } else {
            asm volatile("cp.async.wait_group 0;");
        }
        __syncthreads();

        unsigned aBaseH = (unsigned)__cvta_generic_to_shared(sAh + s * A_STAGE);
        unsigned aBaseL = (unsigned)__cvta_generic_to_shared(sAl + s * A_STAGE);
        unsigned bBaseH = (unsigned)__cvta_generic_to_shared(sBh + s * B_STAGE);
        unsigned bBaseL = (unsigned)__cvta_generic_to_shared(sBl + s * B_STAGE);

#pragma unroll
        for (int kk = 0; kk < BK; kk += 16) {
            unsigned afh[2][4], afl[2][4];
#pragma unroll
            for (int mt = 0; mt < 2; mt++) {
                unsigned off = ((wm + mt * 16 + (lane & 15)) * ASTR + kk + (lane >> 4) * 8) * 2;
                ldm_x4(afh[mt], aBaseH + off);
                ldm_x4(afl[mt], aBaseL + off);
            }
            unsigned bfh[4][4], bfl[4][4];
#pragma unroll
            for (int nt = 0; nt < 4; nt++) {
                unsigned off = ((kk + (lane & 15)) * BSTR + wn + nt * 16 + (lane >> 4) * 8) * 2;
                ldm_x4_t(bfh[nt], bBaseH + off);
                ldm_x4_t(bfl[nt], bBaseL + off);
            }
#pragma unroll
            for (int mt = 0; mt < 2; mt++)
#pragma unroll
                for (int nt = 0; nt < 4; nt++) {
                    mma16816(acc[mt][2 * nt],     afh[mt], &bfh[nt][0]);
                    mma16816(acc[mt][2 * nt + 1], afh[mt], &bfh[nt][2]);
                    mma16816(acc[mt][2 * nt],     afh[mt], &bfl[nt][0]);
                    mma16816(acc[mt][2 * nt + 1], afh[mt], &bfl[nt][2]);
                    mma16816(acc[mt][2 * nt],     afl[mt], &bfh[nt][0]);
                    mma16816(acc[mt][2 * nt + 1], afl[mt], &bfh[nt][2]);
                }
        }
        __syncthreads();
    }

#pragma unroll
    for (int mt = 0; mt < 2; mt++) {
        int row0 = bm + wm + mt * 16 + (lane >> 2);
#pragma unroll
        for (int n8 = 0; n8 < 8; n8++) {
            int col = bn + wn + n8 * 8 + (lane & 3) * 2;
            float b0 = bias[col], b1 = bias[col + 1];
            float2 v0, v1;
            v0.x = acc[mt][n8][0] + b0; v0.y = acc[mt][n8][1] + b1;
            v1.x = acc[mt][n8][2] + b0; v1.y = acc[mt][n8][3] + b1;
            *(float2*)(g_Q + (size_t)row0 * HIDs + col)       = v0;
            *(float2*)(g_Q + (size_t)(row0 + 8) * HIDs + col) = v1;
        }
    }
}

// ---------------------------------------------------------------------------
// K2: pair scores (unchanged from R8)
// ---------------------------------------------------------------------------
__global__ __launch_bounds__(256) void k_dots() {
    int p = blockIdx.x * 8 + (threadIdx.x >> 5);
    int lane = threadIdx.x & 31;
    int b = p / (Msz - 1);
    int i = p - b * (Msz - 1);
    const float* qa = g_Q + ((size_t)b * Msz + i) * HIDs;
    const float* qb = qa + HIDs;
#pragma unroll
    for (int pass = 0; pass < 6; pass++) {
        int d = pass * 128 + lane * 4;
        float4 a4 = *(const float4*)(qa + d);
        float4 b4 = *(const float4*)(qb + d);
        float s = a4.x * b4.x + a4.y * b4.y + a4.z * b4.z + a4.w * b4.w;
#pragma unroll
        for (int off = 8; off; off >>= 1) s += __shfl_xor_sync(0xffffffffu, s, off);
        if ((lane & 15) == 0) {
            int h = pass * 2 + (lane >> 4);
            g_s[(b * NH + h) * Msz + i] = s * (1.0f / 64.0f);
        }
    }
}

// ---------------------------------------------------------------------------
// K3: softmax band + prefix sums. Warp-shuffle double scan (2 syncs).
// ---------------------------------------------------------------------------
__global__ void k_band(const float* __restrict__ prior, const int* __restrict__ mask) {
    int bh = blockIdx.x;
    int b  = bh / NH;
    int i  = threadIdx.x;
    int lane = i & 31, wid = i >> 5;
    __shared__ float  sh_s[Msz];
    __shared__ float  sh_an[Msz];
    __shared__ float  sh_ap[Msz];
    __shared__ double wsum[16];

    sh_s[i] = (i < Msz - 1) ? g_s[bh * Msz + i] : 0.f;
    __syncthreads();

    bool hp = (i > 0)       && (mask[b * Msz + i - 1] > 0);
    bool hn = (i < Msz - 1) && (mask[b * Msz + i + 1] > 0);
    float an = 0.f, ap = 0.f;
    if (hn && hp) {
        float sn = sh_s[i], sp = sh_s[i - 1];
        float m  = fmaxf(sn, sp);
        float en = expf(sn - m), ep = expf(sp - m);
        float z  = en + ep;
        an = en / z;
        ap = ep / z;
    } else if (hn) { an = 1.f; }
    else if (hp)   { ap = 1.f; }
    sh_an[i] = an;
    sh_ap[i] = ap;
    __syncthreads();

    float l = 0.f;
    if (i < Msz - 1) {
        float v    = sqrtf(sh_an[i] * sh_ap[i + 1] + 1e-4f);
        float prs  = prior[((size_t)b * Msz + i) * Msz + (i + 1)];
        float prb  = prior[((size_t)b * Msz + i + 1) * Msz + i];
        float nsup = prs + (1.f - prs) * v;
        float nsub = prb + (1.f - prb) * v;
        g_nasup[bh * Msz + i] = nsup;
        g_nasub[bh * Msz + i] = nsub;
        l = logf(nsup + 1e-9f);
    }

    double v = (double)l;
#pragma unroll
    for (int o = 1; o < 32; o <<= 1) {
        double t = __shfl_up_sync(0xffffffffu, v, o);
        if (lane >= o) v += t;
    }
    if (lane == 31) wsum[wid] = v;
    __syncthreads();
    if (i < 16) {
        double x = wsum[i];
#pragma unroll
        for (int o = 1; o < 16; o <<= 1) {
            double t = __shfl_up_sync(0xffffu, x, o);
            if (i >= o) x += t;
        }
        wsum[i] = x;
    }
    __syncthreads();
    double incl = v + (wid ? wsum[wid - 1] : 0.0);
    g_S[bh * Msz + i] = (float)(incl - (double)l);
}

// ---------------------------------------------------------------------------
// K_FILL (side stream, depends only on prior):
// nbout[.,h,i,k] = p + (1-p)*0.01 everywhere; gout = 1e-4 except diag=generic.
// ---------------------------------------------------------------------------
__global__ __launch_bounds__(256) void k_fill(const float* __restrict__ prior,
                                              float* __restrict__ gout,
                                              float* __restrict__ nbout) {
    int b = blockIdx.y;
    int i = blockIdx.x * 2 + (threadIdx.x >> 7);
    int c = (threadIdx.x & 127) * 4;
    const float SQEPS = 0.01f;

    float4 p = *(const float4*)(prior + ((size_t)b * Msz + i) * Msz + c);
    float nb[4], g[4];
    nb[0] = p.x + (1.f - p.x) * SQEPS; nb[1] = p.y + (1.f - p.y) * SQEPS;
    nb[2] = p.z + (1.f - p.z) * SQEPS; nb[3] = p.w + (1.f - p.w) * SQEPS;
    g[0] = 1e-4f; g[1] = 1e-4f; g[2] = 1e-4f; g[3] = 1e-4f;
    if (i >= c && i < c + 4) g[i - c] = nb[i - c];

    size_t rb = ((size_t)(b * NH) * Msz + i) * Msz + c;
#pragma unroll
    for (int h = 0; h < NH; h++) {
        size_t off = rb + (size_t)h * Msz * Msz;
        stcs4(gout + off,  g[0],  g[1],  g[2],  g[3]);
        stcs4(nbout + off, nb[0], nb[1], nb[2], nb[3]);
    }
}

// ---------------------------------------------------------------------------
// K_BANDW: warp per (b,h,i) row. Walk k outward from diagonal writing
// exp(S_k - S_i)+1e-4 symmetrically while any lane in the 32-chunk passes
// the -18 cutoff. Lane 0 patches nbout super/sub-diagonal.
// ---------------------------------------------------------------------------
__global__ __launch_bounds__(256) void k_bandw(float* __restrict__ gout,
                                               float* __restrict__ nbout) {
    int w    = blockIdx.x * 8 + (threadIdx.x >> 5);   // 0 .. BHsz*Msz-1
    int lane = threadIdx.x & 31;
    int bh   = w >> 9;
    int i    = w & (Msz - 1);
    const float* Srow = g_S + bh * Msz;
    float Si = Srow[i];
    size_t base = (size_t)bh * Msz * Msz;
    float* grow = gout + base + (size_t)i * Msz;

    if (lane == 0 && i < Msz - 1) {
        nbout[base + (size_t)i * Msz + i + 1]       = g_nasup[bh * Msz + i];
        nbout[base + (size_t)(i + 1) * Msz + i]     = g_nasub[bh * Msz + i];
    }

    for (int j0 = 1; ; j0 += 32) {
        int k = i + j0 + lane;
        bool act = k < Msz;
        float dS = act ? (Srow[k] - Si) : -1e30f;
        bool wr = dS > -18.f;
        if (wr) {
            float e = __expf(dS) + 1e-4f;
            grow[k] = e;
            gout[base + (size_t)k * Msz + i] = e;
        }
        if (__ballot_sync(0xffffffffu, wr) != 0xffffffffu) break;
    }
}

extern "C" void kernel_launch(void* const* d_in, const int* in_sizes, int n_in,
                              void* d_out, int out_size) {
    const float* X     = (const float*)d_in[0];
    const float* prior = (const float*)d_in[1];
    const float* Wq    = (const float*)d_in[2];
    const float* bq    = (const float*)d_in[3];
    const int*   mask  = (const int*)d_in[4];
    float* out   = (float*)d_out;
    float* gout  = out;
    float* nbout = out + (size_t)BHsz * Msz * Msz;

    static cudaStream_t s_side = nullptr;
    static cudaEvent_t ev_fork = nullptr, ev_join = nullptr;
    if (s_side == nullptr) {
        cudaStreamCreateWithFlags(&s_side, cudaStreamNonBlocking);
        cudaEventCreateWithFlags(&ev_fork, cudaEventDisableTiming);
        cudaEventCreateWithFlags(&ev_join, cudaEventDisableTiming);
    }

    __nv_bfloat16 *dAh, *dAl, *dWh, *dWl;
    cudaGetSymbolAddress((void**)&dAh, g_Ah);
    cudaGetSymbolAddress((void**)&dAl, g_Al);
    cudaGetSymbolAddress((void**)&dWh, g_Wh);
    cudaGetSymbolAddress((void**)&dWl, g_Wl);

    cudaFuncSetAttribute(k_gemm_mma, cudaFuncAttributeMaxDynamicSharedMemorySize,
                         SMEM_BYTES);

    // fork side stream: fill runs concurrently with the compute chain
    cudaEventRecord(ev_fork, 0);
    cudaStreamWaitEvent(s_side, ev_fork, 0);
    k_fill<<<dim3(Msz / 2, Bsz), 256, 0, s_side>>>(prior, gout, nbout);
    cudaEventRecord(ev_join, s_side);

    int nX = Bsz * Msz * HIDs;
    int nW = HIDs * HIDs;
    k_cvt<<<(nX / 4 + 255) / 256, 256>>>(X, dAh, dAl, nX);
    k_cvt<<<(nW / 4 + 255) / 256, 256>>>(Wq, dWh, dWl, nW);
    k_gemm_mma<<<dim3(HIDs / BN, (Bsz * Msz) / BM), 256, SMEM_BYTES>>>(bq);
    k_dots<<<(Bsz * (Msz - 1)) / 8, 256>>>();
    k_band<<<BHsz, Msz>>>(prior, mask);

    // join, then band writers (overwrite near-diagonal region)
    cudaStreamWaitEvent(0, ev_join, 0);
    k_bandw<<<(BHsz * Msz) / 8, 256>>>(gout, nbout);
}

// round 13
// speedup vs baseline: 1.1294x; 1.1294x over previous
#include <cuda_runtime.h>
#include <cuda_bf16.h>
#include <cstdint>
#include <cstddef>
#include <math.h>

#define Bsz 16
#define Msz 512
#define HIDs 768
#define NH 12
#define HD 64
#define BHsz (Bsz*NH)

#define BM 128
#define BN 128
#define BK 32
#define ASTR 40
#define BSTR 136
#define NIT (HIDs/BK)
#define A_STAGE (BM*ASTR)
#define B_STAGE (BK*BSTR)
#define OFF_AH 0
#define OFF_AL (2*A_STAGE)
#define OFF_BH (4*A_STAGE)
#define OFF_BL (4*A_STAGE + 2*B_STAGE)
#define SMEM_BYTES ((4*A_STAGE + 4*B_STAGE) * 2)

// Scratch (__device__ globals; no allocation allowed)
__device__ float g_Q[(size_t)Bsz*Msz*HIDs];
__device__ __nv_bfloat16 g_Ah[(size_t)Bsz*Msz*HIDs];
__device__ __nv_bfloat16 g_Al[(size_t)Bsz*Msz*HIDs];
__device__ __nv_bfloat16 g_Wh[HIDs*HIDs];
__device__ __nv_bfloat16 g_Wl[HIDs*HIDs];
__device__ float g_s[BHsz*Msz];
__device__ float g_nasup[BHsz*Msz];
__device__ float g_nasub[BHsz*Msz];
__device__ float g_S[BHsz*Msz];

// ---------------------------------------------------------------------------
// Split fp32 -> bf16 hi + bf16 lo
// ---------------------------------------------------------------------------
__global__ void k_cvt(const float* __restrict__ x, __nv_bfloat16* __restrict__ hi,
                      __nv_bfloat16* __restrict__ lo, int n) {
    int idx = (blockIdx.x * blockDim.x + threadIdx.x) * 4;
    if (idx >= n) return;
    float4 v = *(const float4*)(x + idx);
    __nv_bfloat16 h0 = __float2bfloat16(v.x), h1 = __float2bfloat16(v.y);
    __nv_bfloat16 h2 = __float2bfloat16(v.z), h3 = __float2bfloat16(v.w);
    __nv_bfloat16 l0 = __float2bfloat16(v.x - __bfloat162float(h0));
    __nv_bfloat16 l1 = __float2bfloat16(v.y - __bfloat162float(h1));
    __nv_bfloat16 l2 = __float2bfloat16(v.z - __bfloat162float(h2));
    __nv_bfloat16 l3 = __float2bfloat16(v.w - __bfloat162float(h3));
    __nv_bfloat162 hp0, hp1, lp0, lp1;
    hp0.x = h0; hp0.y = h1; hp1.x = h2; hp1.y = h3;
    lp0.x = l0; lp0.y = l1; lp1.x = l2; lp1.y = l3;
    *(__nv_bfloat162*)(hi + idx)     = hp0;
    *(__nv_bfloat162*)(hi + idx + 2) = hp1;
    *(__nv_bfloat162*)(lo + idx)     = lp0;
    *(__nv_bfloat162*)(lo + idx + 2) = lp1;
}

// ---------------------------------------------------------------------------
// Helpers
// ---------------------------------------------------------------------------
__device__ __forceinline__ void cp16(__nv_bfloat16* s, const __nv_bfloat16* g) {
    unsigned sa = (unsigned)__cvta_generic_to_shared(s);
    asm volatile("cp.async.ca.shared.global [%0], [%1], 16;\n" :: "r"(sa), "l"(g));
}
__device__ __forceinline__ void ldm_x4(unsigned* r, unsigned a) {
    asm volatile("ldmatrix.sync.aligned.m8n8.x4.shared.b16 {%0,%1,%2,%3}, [%4];"
                 : "=r"(r[0]), "=r"(r[1]), "=r"(r[2]), "=r"(r[3]) : "r"(a));
}
__device__ __forceinline__ void ldm_x4_t(unsigned* r, unsigned a) {
    asm volatile("ldmatrix.sync.aligned.m8n8.x4.trans.shared.b16 {%0,%1,%2,%3}, [%4];"
                 : "=r"(r[0]), "=r"(r[1]), "=r"(r[2]), "=r"(r[3]) : "r"(a));
}
__device__ __forceinline__ void mma16816(float* c, const unsigned* a, const unsigned* b) {
    asm volatile(
        "mma.sync.aligned.m16n8k16.row.col.f32.bf16.bf16.f32 "
        "{%0,%1,%2,%3}, {%4,%5,%6,%7}, {%8,%9}, {%0,%1,%2,%3};"
        : "+f"(c[0]), "+f"(c[1]), "+f"(c[2]), "+f"(c[3])
        : "r"(a[0]), "r"(a[1]), "r"(a[2]), "r"(a[3]), "r"(b[0]), "r"(b[1]));
}
__device__ __forceinline__ void stcs4(float* p, float a, float b, float c, float d) {
    asm volatile("st.global.cs.v4.f32 [%0], {%1,%2,%3,%4};"
                 :: "l"(p), "f"(a), "f"(b), "f"(c), "f"(d) : "memory");
}

// ---------------------------------------------------------------------------
// K1: Q = X @ Wq + bq via bf16-split tensor cores.
// MMA schedule: pass-outermost (hh, hl, lh) so each accumulator's reuse
// distance is 16 independent MMAs instead of back-to-back chains of 3.
// ---------------------------------------------------------------------------
__global__ __launch_bounds__(256) void k_gemm_mma(const float* __restrict__ bias) {
    extern __shared__ __align__(16) __nv_bfloat16 smem[];
    __nv_bfloat16* sAh = smem + OFF_AH;
    __nv_bfloat16* sAl = smem + OFF_AL;
    __nv_bfloat16* sBh = smem + OFF_BH;
    __nv_bfloat16* sBl = smem + OFF_BL;

    int tid  = threadIdx.x;
    int bm   = blockIdx.y * BM;
    int bn   = blockIdx.x * BN;
    int warp = tid >> 5, lane = tid & 31;
    int wm = (warp & 3) * 32;
    int wn = (warp >> 2) * 64;

    int arow = tid >> 1, acol = (tid & 1) * 16;
    int brow = tid >> 3, bcol = (tid & 7) * 16;

    float acc[2][8][4];
#pragma unroll
    for (int m = 0; m < 2; m++)
#pragma unroll
        for (int n = 0; n < 8; n++)
#pragma unroll
            for (int j = 0; j < 4; j++) acc[m][n][j] = 0.f;

    {
        const __nv_bfloat16* gah = g_Ah + (size_t)(bm + arow) * HIDs + acol;
        const __nv_bfloat16* gal = g_Al + (size_t)(bm + arow) * HIDs + acol;
        const __nv_bfloat16* gbh = g_Wh + (size_t)brow * HIDs + bn + bcol;
        const __nv_bfloat16* gbl = g_Wl + (size_t)brow * HIDs + bn + bcol;
        __nv_bfloat16* dah = sAh + arow * ASTR + acol;
        __nv_bfloat16* dal = sAl + arow * ASTR + acol;
        __nv_bfloat16* dbh = sBh + brow * BSTR + bcol;
        __nv_bfloat16* dbl = sBl + brow * BSTR + bcol;
        cp16(dah, gah); cp16(dah + 8, gah + 8);
        cp16(dal, gal); cp16(dal + 8, gal + 8);
        cp16(dbh, gbh); cp16(dbh + 8, gbh + 8);
        cp16(dbl, gbl); cp16(dbl + 8, gbl + 8);
        asm volatile("cp.async.commit_group;");
    }

    for (int it = 0; it < NIT; it++) {
        int s = it & 1;
        if (it + 1 < NIT) {
            int k0 = (it + 1) * BK, ns = s ^ 1;
            const __nv_bfloat16* gah = g_Ah + (size_t)(bm + arow) * HIDs + k0 + acol;
            const __nv_bfloat16* gal = g_Al + (size_t)(bm + arow) * HIDs + k0 + acol;
            const __nv_bfloat16* gbh = g_Wh + (size_t)(k0 + brow) * HIDs + bn + bcol;
            const __nv_bfloat16* gbl = g_Wl + (size_t)(k0 + brow) * HIDs + bn + bcol;
            __nv_bfloat16* dah = sAh + ns * A_STAGE + arow * ASTR + acol;
            __nv_bfloat16* dal = sAl + ns * A_STAGE + arow * ASTR + acol;
            __nv_bfloat16* dbh = sBh + ns * B_STAGE + brow * BSTR + bcol;
            __nv_bfloat16* dbl = sBl + ns * B_STAGE + brow * BSTR + bcol;
            cp16(dah, gah); cp16(dah + 8, gah + 8);
            cp16(dal, gal); cp16(dal + 8, gal + 8);
            cp16(dbh, gbh); cp16(dbh + 8, gbh + 8);
            cp16(dbl, gbl); cp16(dbl + 8, gbl + 8);
            asm volatile("cp.async.commit_group;");
            asm volatile("cp.async.wait_group 1;");
        } else {
            asm volatile("cp.async.wait_group 0;");
        }
        __syncthreads();

        unsigned aBaseH = (unsigned)__cvta_generic_to_shared(sAh + s * A_STAGE);
        unsigned aBaseL = (unsigned)__cvta_generic_to_shared(sAl + s * A_STAGE);
        unsigned bBaseH = (unsigned)__cvta_generic_to_shared(sBh + s * B_STAGE);
        unsigned bBaseL = (unsigned)__cvta_generic_to_shared(sBl + s * B_STAGE);

#pragma unroll
        for (int kk = 0; kk < BK; kk += 16) {
            unsigned afh[2][4], afl[2][4];
#pragma unroll
            for (int mt = 0; mt < 2; mt++) {
                unsigned off = ((wm + mt * 16 + (lane & 15)) * ASTR + kk + (lane >> 4) * 8) * 2;
                ldm_x4(afh[mt], aBaseH + off);
                ldm_x4(afl[mt], aBaseL + off);
            }
            unsigned bfh[4][4], bfl[4][4];
#pragma unroll
            for (int nt = 0; nt < 4; nt++) {
                unsigned off = ((kk + (lane & 15)) * BSTR + wn + nt * 16 + (lane >> 4) * 8) * 2;
                ldm_x4_t(bfh[nt], bBaseH + off);
                ldm_x4_t(bfl[nt], bBaseL + off);
            }
            // pass 0: Ah*Bh  (16 independent MMAs)
#pragma unroll
            for (int mt = 0; mt < 2; mt++)
#pragma unroll
                for (int nt = 0; nt < 4; nt++) {
                    mma16816(acc[mt][2 * nt],     afh[mt], &bfh[nt][0]);
                    mma16816(acc[mt][2 * nt + 1], afh[mt], &bfh[nt][2]);
                }
            // pass 1: Ah*Bl
#pragma unroll
            for (int mt = 0; mt < 2; mt++)
#pragma unroll
                for (int nt = 0; nt < 4; nt++) {
                    mma16816(acc[mt][2 * nt],     afh[mt], &bfl[nt][0]);
                    mma16816(acc[mt][2 * nt + 1], afh[mt], &bfl[nt][2]);
                }
            // pass 2: Al*Bh
#pragma unroll
            for (int mt = 0; mt < 2; mt++)
#pragma unroll
                for (int nt = 0; nt < 4; nt++) {
                    mma16816(acc[mt][2 * nt],     afl[mt], &bfh[nt][0]);
                    mma16816(acc[mt][2 * nt + 1], afl[mt], &bfh[nt][2]);
                }
        }
        __syncthreads();
    }

#pragma unroll
    for (int mt = 0; mt < 2; mt++) {
        int row0 = bm + wm + mt * 16 + (lane >> 2);
#pragma unroll
        for (int n8 = 0; n8 < 8; n8++) {
            int col = bn + wn + n8 * 8 + (lane & 3) * 2;
            float b0 = bias[col], b1 = bias[col + 1];
            float2 v0, v1;
            v0.x = acc[mt][n8][0] + b0; v0.y = acc[mt][n8][1] + b1;
            v1.x = acc[mt][n8][2] + b0; v1.y = acc[mt][n8][3] + b1;
            *(float2*)(g_Q + (size_t)row0 * HIDs + col)       = v0;
            *(float2*)(g_Q + (size_t)(row0 + 8) * HIDs + col) = v1;
        }
    }
}

// ---------------------------------------------------------------------------
// K2: pair scores
// ---------------------------------------------------------------------------
__global__ __launch_bounds__(256) void k_dots() {
    int p = blockIdx.x * 8 + (threadIdx.x >> 5);
    int lane = threadIdx.x & 31;
    int b = p / (Msz - 1);
    int i = p - b * (Msz - 1);
    const float* qa = g_Q + ((size_t)b * Msz + i) * HIDs;
    const float* qb = qa + HIDs;
#pragma unroll
    for (int pass = 0; pass < 6; pass++) {
        int d = pass * 128 + lane * 4;
        float4 a4 = *(const float4*)(qa + d);
        float4 b4 = *(const float4*)(qb + d);
        float s = a4.x * b4.x + a4.y * b4.y + a4.z * b4.z + a4.w * b4.w;
#pragma unroll
        for (int off = 8; off; off >>= 1) s += __shfl_xor_sync(0xffffffffu, s, off);
        if ((lane & 15) == 0) {
            int h = pass * 2 + (lane >> 4);
            g_s[(b * NH + h) * Msz + i] = s * (1.0f / 64.0f);
        }
    }
}

// ---------------------------------------------------------------------------
// K3: softmax band + prefix sums (warp-shuffle scan, verified in R9)
// ---------------------------------------------------------------------------
__global__ void k_band(const float* __restrict__ prior, const int* __restrict__ mask) {
    int bh = blockIdx.x;
    int b  = bh / NH;
    int i  = threadIdx.x;
    int lane = i & 31, wid = i >> 5;
    __shared__ float  sh_s[Msz];
    __shared__ float  sh_an[Msz];
    __shared__ float  sh_ap[Msz];
    __shared__ double wsum[16];

    sh_s[i] = (i < Msz - 1) ? g_s[bh * Msz + i] : 0.f;
    __syncthreads();

    bool hp = (i > 0)       && (mask[b * Msz + i - 1] > 0);
    bool hn = (i < Msz - 1) && (mask[b * Msz + i + 1] > 0);
    float an = 0.f, ap = 0.f;
    if (hn && hp) {
        float sn = sh_s[i], sp = sh_s[i - 1];
        float m  = fmaxf(sn, sp);
        float en = expf(sn - m), ep = expf(sp - m);
        float z  = en + ep;
        an = en / z;
        ap = ep / z;
    } else if (hn) { an = 1.f; }
    else if (hp)   { ap = 1.f; }
    sh_an[i] = an;
    sh_ap[i] = ap;
    __syncthreads();

    float l = 0.f;
    if (i < Msz - 1) {
        float v    = sqrtf(sh_an[i] * sh_ap[i + 1] + 1e-4f);
        float prs  = prior[((size_t)b * Msz + i) * Msz + (i + 1)];
        float prb  = prior[((size_t)b * Msz + i + 1) * Msz + i];
        float nsup = prs + (1.f - prs) * v;
        float nsub = prb + (1.f - prb) * v;
        g_nasup[bh * Msz + i] = nsup;
        g_nasub[bh * Msz + i] = nsub;
        l = logf(nsup + 1e-9f);
    }

    double v = (double)l;
#pragma unroll
    for (int o = 1; o < 32; o <<= 1) {
        double t = __shfl_up_sync(0xffffffffu, v, o);
        if (lane >= o) v += t;
    }
    if (lane == 31) wsum[wid] = v;
    __syncthreads();
    if (i < 16) {
        double x = wsum[i];
#pragma unroll
        for (int o = 1; o < 16; o <<= 1) {
            double t = __shfl_up_sync(0xffffu, x, o);
            if (i >= o) x += t;
        }
        wsum[i] = x;
    }
    __syncthreads();
    double incl = v + (wid ? wsum[wid - 1] : 0.0);
    g_S[bh * Msz + i] = (float)(incl - (double)l);
}

// ---------------------------------------------------------------------------
// K4: output writer (R8 layout: each st.v4 covers 32 consecutive lanes)
// ---------------------------------------------------------------------------
__global__ __launch_bounds__(256) void k_out(const float* __restrict__ prior,
                                             float* __restrict__ gout,
                                             float* __restrict__ nbout) {
    int b = blockIdx.y;
    __shared__ float shS[NH][Msz];  // 24 KB
    const float* Sbase = g_S + (size_t)b * NH * Msz;
    for (int idx = threadIdx.x * 4; idx < NH * Msz; idx += 256 * 4)
        *(float4*)(&shS[0][0] + idx) = *(const float4*)(Sbase + idx);
    __syncthreads();

    int r  = threadIdx.x >> 6;
    int i  = blockIdx.x * 4 + r;
    int c0 = (threadIdx.x & 63) * 4;
    int c1 = c0 + 256;
    const float SQEPS = 0.01f;

    const float* prow = prior + ((size_t)b * Msz + i) * Msz;
    float4 p0 = *(const float4*)(prow + c0);
    float4 p1 = *(const float4*)(prow + c1);
    float nbg0[4], nbg1[4];
    nbg0[0] = p0.x + (1.f - p0.x) * SQEPS; nbg0[1] = p0.y + (1.f - p0.y) * SQEPS;
    nbg0[2] = p0.z + (1.f - p0.z) * SQEPS; nbg0[3] = p0.w + (1.f - p0.w) * SQEPS;
    nbg1[0] = p1.x + (1.f - p1.x) * SQEPS; nbg1[1] = p1.y + (1.f - p1.y) * SQEPS;
    nbg1[2] = p1.z + (1.f - p1.z) * SQEPS; nbg1[3] = p1.w + (1.f - p1.w) * SQEPS;

    size_t rowbase = ((size_t)(b * NH) * Msz + i) * Msz;

    for (int h = 0; h < NH; h++) {
        int bh   = b * NH + h;
        float Si = shS[h][i];
        size_t off = rowbase + (size_t)h * Msz * Msz;

#pragma unroll
        for (int ch = 0; ch < 2; ch++) {
            int c = ch ? c1 : c0;
            const float* nbg = ch ? nbg1 : nbg0;
            float4 s4 = *(float4*)&shS[h][c];
            float sv[4]; sv[0] = s4.x; sv[1] = s4.y; sv[2] = s4.z; sv[3] = s4.w;
            float go[4], no[4];
#pragma unroll
            for (int j = 0; j < 4; j++) {
                int k    = c + j;
                float dS = (k > i) ? (sv[j] - Si) : (Si - sv[j]);
                float e  = (dS > -18.f) ? __expf(dS) : 0.f;
                go[j] = e + 1e-4f;
                no[j] = nbg[j];
            }
            if (i >= c && i < c + 4)                       go[i - c] = nbg[i - c];
            if (i + 1 >= c && i + 1 < c + 4)               no[i + 1 - c] = g_nasup[bh * Msz + i];
            if (i >= 1 && i - 1 >= c && i - 1 < c + 4)     no[i - 1 - c] = g_nasub[bh * Msz + (i - 1)];

            stcs4(gout + off + c,  go[0], go[1], go[2], go[3]);
            stcs4(nbout + off + c, no[0], no[1], no[2], no[3]);
        }
    }
}

extern "C" void kernel_launch(void* const* d_in, const int* in_sizes, int n_in,
                              void* d_out, int out_size) {
    const float* X     = (const float*)d_in[0];
    const float* prior = (const float*)d_in[1];
    const float* Wq    = (const float*)d_in[2];
    const float* bq    = (const float*)d_in[3];
    const int*   mask  = (const int*)d_in[4];
    float* out   = (float*)d_out;
    float* gout  = out;
    float* nbout = out + (size_t)BHsz * Msz * Msz;

    __nv_bfloat16 *dAh, *dAl, *dWh, *dWl;
    cudaGetSymbolAddress((void**)&dAh, g_Ah);
    cudaGetSymbolAddress((void**)&dAl, g_Al);
    cudaGetSymbolAddress((void**)&dWh, g_Wh);
    cudaGetSymbolAddress((void**)&dWl, g_Wl);

    cudaFuncSetAttribute(k_gemm_mma, cudaFuncAttributeMaxDynamicSharedMemorySize,
                         SMEM_BYTES);

    int nX = Bsz * Msz * HIDs;
    int nW = HIDs * HIDs;
    k_cvt<<<(nX / 4 + 255) / 256, 256>>>(X, dAh, dAl, nX);
    k_cvt<<<(nW / 4 + 255) / 256, 256>>>(Wq, dWh, dWl, nW);
    k_gemm_mma<<<dim3(HIDs / BN, (Bsz * Msz) / BM), 256, SMEM_BYTES>>>(bq);
    k_dots<<<(Bsz * (Msz - 1)) / 8, 256>>>();
    k_band<<<BHsz, Msz>>>(prior, mask);
    k_out<<<dim3(Msz / 4, Bsz), 256>>>(prior, gout, nbout);
}